// round 14
// baseline (speedup 1.0000x reference)
#include <cuda_runtime.h>
#include <cuda_fp16.h>
#include <stdint.h>

// ------------------------------------------------------------------
// Problem constants
// ------------------------------------------------------------------
#define M_TOTAL 8192      // B*S = 4*2048 tokens
#define N_TOTAL 4096      // OUT
#define K_TOTAL 4096      // IN
#define GRP     256

#define BM 128
#define BN 128
#define BK 64             // halves per K-chunk (128 bytes/row -> SW128)
#define KITERS (K_TOTAL / BK)   // 64
#define A_BYTES 16384           // 128 rows x 128 B
#define B_BYTES 16384           // 128 rows x 128 B
#define STAGE_BYTES (A_BYTES + B_BYTES)          // 32 KB
#define SMEM_BYTES (3 * STAGE_BYTES)             // 96 KB -> 2 CTAs/SM

// ------------------------------------------------------------------
// Scratch (device globals; no allocation allowed)
// ------------------------------------------------------------------
__device__ __half g_aq[(size_t)M_TOTAL * K_TOTAL];   // (q - zp), exact in fp16
__device__ __half g_w16[(size_t)N_TOTAL * K_TOTAL];  // (w - zero)*scale in fp16
__device__ float  g_sx[M_TOTAL];                     // per-token scale
__device__ int    g_w_is_int8;                       // weight buffer dtype flag

// ------------------------------------------------------------------
// helpers
// ------------------------------------------------------------------
__device__ __forceinline__ uint32_t smem_u32(const void* p) {
    uint32_t a;
    asm("{ .reg .u64 t; cvta.to.shared.u64 t, %1; cvt.u32.u64 %0, t; }"
        : "=r"(a) : "l"(p));
    return a;
}

__device__ __forceinline__ uint32_t swz(uint32_t off) {
    return off ^ ((off >> 3) & 0x70);
}

// ldmatrix.x4 with compile-time byte offset folded into the operand
#define LDSM_X4_OFF(ADDR, OFF, R0, R1, R2, R3)                                   \
    asm volatile("ldmatrix.sync.aligned.m8n8.x4.shared.b16 {%0,%1,%2,%3}, [%4+" #OFF "];" \
                 : "=r"(R0), "=r"(R1), "=r"(R2), "=r"(R3) : "r"(ADDR))

// ------------------------------------------------------------------
// Kernel 0: detect weight buffer dtype (int32-promoted vs raw int8)
// ------------------------------------------------------------------
__global__ void sniff_kernel(const int* __restrict__ w) {
    __shared__ int bad;
    if (threadIdx.x == 0) bad = 0;
    __syncthreads();
    int v = w[threadIdx.x * 16000];
    if (v < -8 || v > 7) atomicOr(&bad, 1);
    __syncthreads();
    if (threadIdx.x == 0) g_w_is_int8 = bad;
}

// ------------------------------------------------------------------
// Kernel 1: per-token asymmetric int8 fake-quant -> (q - zp) in fp16
// ------------------------------------------------------------------
__global__ void __launch_bounds__(256) quant_kernel(const float* __restrict__ x) {
    const int t = blockIdx.x;
    const int tid = threadIdx.x;
    const float4* xp = (const float4*)x + (size_t)t * (K_TOTAL / 4);

    float4 v[4];
    float mn = 0.0f, mx = 0.0f;
#pragma unroll
    for (int i = 0; i < 4; i++) {
        v[i] = xp[i * 256 + tid];
        mn = fminf(mn, fminf(fminf(v[i].x, v[i].y), fminf(v[i].z, v[i].w)));
        mx = fmaxf(mx, fmaxf(fmaxf(v[i].x, v[i].y), fmaxf(v[i].z, v[i].w)));
    }
#pragma unroll
    for (int o = 16; o; o >>= 1) {
        mn = fminf(mn, __shfl_xor_sync(0xffffffffu, mn, o));
        mx = fmaxf(mx, __shfl_xor_sync(0xffffffffu, mx, o));
    }
    __shared__ float smn[8], smx[8], s_scale, s_zp;
    const int wid = tid >> 5, lid = tid & 31;
    if (lid == 0) { smn[wid] = mn; smx[wid] = mx; }
    __syncthreads();
    if (tid == 0) {
        float a = smn[0], b = smx[0];
#pragma unroll
        for (int i = 1; i < 8; i++) { a = fminf(a, smn[i]); b = fmaxf(b, smx[i]); }
        float scale = fmaxf((b - a) / 255.0f, 1.1920929e-07f);
        float zp = -128.0f - rintf(a / scale);
        zp = fminf(fmaxf(zp, -128.0f), 127.0f);
        s_scale = scale; s_zp = zp;
        g_sx[t] = scale;
    }
    __syncthreads();
    const float scale = s_scale, zp = s_zp;

    __half* aqp = g_aq + (size_t)t * K_TOTAL;
#pragma unroll
    for (int i = 0; i < 4; i++) {
        float qx = fminf(fmaxf(rintf(v[i].x / scale) + zp, -128.0f), 127.0f) - zp;
        float qy = fminf(fmaxf(rintf(v[i].y / scale) + zp, -128.0f), 127.0f) - zp;
        float qz = fminf(fmaxf(rintf(v[i].z / scale) + zp, -128.0f), 127.0f) - zp;
        float qw = fminf(fmaxf(rintf(v[i].w / scale) + zp, -128.0f), 127.0f) - zp;
        __half2 h0 = __floats2half2_rn(qx, qy);
        __half2 h1 = __floats2half2_rn(qz, qw);
        uint2 u;
        u.x = *reinterpret_cast<uint32_t*>(&h0);
        u.y = *reinterpret_cast<uint32_t*>(&h1);
        ((uint2*)aqp)[i * 256 + tid] = u;
    }
}

// ------------------------------------------------------------------
// Kernel 2: groupwise int4 weight dequant -> fp16 (dtype-adaptive)
// ------------------------------------------------------------------
__global__ void __launch_bounds__(256) wdq_kernel(const void* __restrict__ wraw,
                                                  const float* __restrict__ scales,
                                                  const float* __restrict__ zeros) {
    const int idx = blockIdx.x * 256 + threadIdx.x;
    const size_t base = (size_t)idx * 8;
    const int o = (int)(base >> 12);
    const int g = (int)((base & (K_TOTAL - 1)) >> 8);
    const float s = scales[o * (K_TOTAL / GRP) + g];
    const float z = zeros[o * (K_TOTAL / GRP) + g];

    float wv[8];
    if (g_w_is_int8) {
        const char4* wp = (const char4*)((const int8_t*)wraw + base);
        char4 c0 = wp[0], c1 = wp[1];
        wv[0] = c0.x; wv[1] = c0.y; wv[2] = c0.z; wv[3] = c0.w;
        wv[4] = c1.x; wv[5] = c1.y; wv[6] = c1.z; wv[7] = c1.w;
    } else {
        const int4* wp = (const int4*)((const int*)wraw + base);
        int4 a = wp[0], b = wp[1];
        wv[0] = (float)a.x; wv[1] = (float)a.y; wv[2] = (float)a.z; wv[3] = (float)a.w;
        wv[4] = (float)b.x; wv[5] = (float)b.y; wv[6] = (float)b.z; wv[7] = (float)b.w;
    }

    __half2 h0 = __floats2half2_rn((wv[0] - z) * s, (wv[1] - z) * s);
    __half2 h1 = __floats2half2_rn((wv[2] - z) * s, (wv[3] - z) * s);
    __half2 h2 = __floats2half2_rn((wv[4] - z) * s, (wv[5] - z) * s);
    __half2 h3 = __floats2half2_rn((wv[6] - z) * s, (wv[7] - z) * s);
    uint4 u;
    u.x = *reinterpret_cast<uint32_t*>(&h0);
    u.y = *reinterpret_cast<uint32_t*>(&h1);
    u.z = *reinterpret_cast<uint32_t*>(&h2);
    u.w = *reinterpret_cast<uint32_t*>(&h3);
    *((uint4*)(g_w16 + base)) = u;
}

// ------------------------------------------------------------------
// Kernel 3: HMMA fp16 GEMM, 128x128 CTA tile, 128 threads (4 warps,
// 2x2 grid, 64x64 warp tile), 3-stage cp.async, unroll-by-3 mainloop,
// single-base XOR ldmatrix addressing. 2 CTAs/SM, 256-reg budget.
// ------------------------------------------------------------------
__global__ void __launch_bounds__(128, 2) gemm_kernel(const float* __restrict__ bias,
                                                      float* __restrict__ out) {
    extern __shared__ char smem[];
    const uint32_t sb = smem_u32(smem);
    const int tid = threadIdx.x;
    const int lane = tid & 31, wid = tid >> 5;
    const int wm = wid >> 1, wn = wid & 1;           // warp grid 2 x 2
    const int g = lane >> 2, tg = lane & 3;
    const int row0 = blockIdx.y * BM;                // token (M)
    const int col0 = blockIdx.x * BN;                // out-feature (N)

    float acc[4][8][4];
#pragma unroll
    for (int a = 0; a < 4; a++)
#pragma unroll
        for (int b = 0; b < 8; b++)
#pragma unroll
            for (int c = 0; c < 4; c++) acc[a][b][c] = 0.0f;

    // advancing cp.async source pointers (+8 uint4 = 128 B per K-iter)
    const int ldr = tid >> 3, ldc = tid & 7;         // 16 rows x 8 cols of 16B
    const uint4* gA = (const uint4*)g_aq  + (size_t)(row0 + ldr) * 512 + ldc;
    const uint4* gB = (const uint4*)g_w16 + (size_t)(col0 + ldr) * 512 + ldc;
    const uint32_t sdst = sb + swz(ldr * 128 + ldc * 16);

    // A: 8 x 16B (rows ldr+16i), B: 8 x 16B
#define LOAD_TILE(SOFF)                                                        \
    {                                                                          \
        _Pragma("unroll")                                                      \
        for (int i = 0; i < 8; i++)                                            \
            asm volatile("cp.async.cg.shared.global [%0], [%1], 16;"           \
                :: "r"(sdst + (SOFF) + i * 2048), "l"(gA + i * 8192));         \
        _Pragma("unroll")                                                      \
        for (int i = 0; i < 8; i++)                                            \
            asm volatile("cp.async.cg.shared.global [%0], [%1], 16;"           \
                :: "r"(sdst + (SOFF) + A_BYTES + i * 2048), "l"(gB + i * 8192));\
        asm volatile("cp.async.commit_group;" ::: "memory");                   \
        gA += 8; gB += 8;                                                      \
    }

    // single base register per operand (stage offset is an immediate)
    const uint32_t aRow = wm * 64 + (lane & 15);
    const uint32_t bRow = wn * 64 + (lane & 15);
    const uint32_t laneHalf = lane >> 4;             // 0 or 1 (k or k+8)
    const uint32_t Abase = sb + aRow * 128 + ((laneHalf ^ (aRow & 7)) * 16);
    const uint32_t Bbase = sb + A_BYTES + bRow * 128 + ((laneHalf ^ (bRow & 7)) * 16);

    auto compute_stage = [&](const uint32_t so) {
        const uint32_t As = Abase + so;
        const uint32_t Bs = Bbase + so;
#pragma unroll
        for (int kk = 0; kk < 4; kk++) {
            const uint32_t xa = As ^ (kk * 32);
            const uint32_t xb = Bs ^ (kk * 32);
            uint32_t aF[4][4], bF[8][2];
            LDSM_X4_OFF(xa, 0,    aF[0][0], aF[0][1], aF[0][2], aF[0][3]);
            LDSM_X4_OFF(xa, 2048, aF[1][0], aF[1][1], aF[1][2], aF[1][3]);
            LDSM_X4_OFF(xa, 4096, aF[2][0], aF[2][1], aF[2][2], aF[2][3]);
            LDSM_X4_OFF(xa, 6144, aF[3][0], aF[3][1], aF[3][2], aF[3][3]);
            {
                uint32_t r0, r1, r2, r3;
                LDSM_X4_OFF(xb, 0, r0, r1, r2, r3);
                bF[0][0] = r0; bF[0][1] = r2; bF[1][0] = r1; bF[1][1] = r3;
            }
            {
                uint32_t r0, r1, r2, r3;
                LDSM_X4_OFF(xb, 2048, r0, r1, r2, r3);
                bF[2][0] = r0; bF[2][1] = r2; bF[3][0] = r1; bF[3][1] = r3;
            }
            {
                uint32_t r0, r1, r2, r3;
                LDSM_X4_OFF(xb, 4096, r0, r1, r2, r3);
                bF[4][0] = r0; bF[4][1] = r2; bF[5][0] = r1; bF[5][1] = r3;
            }
            {
                uint32_t r0, r1, r2, r3;
                LDSM_X4_OFF(xb, 6144, r0, r1, r2, r3);
                bF[6][0] = r0; bF[6][1] = r2; bF[7][0] = r1; bF[7][1] = r3;
            }
#pragma unroll
            for (int mi = 0; mi < 4; mi++)
#pragma unroll
                for (int nj = 0; nj < 8; nj++)
                    asm volatile(
                        "mma.sync.aligned.m16n8k16.row.col.f32.f16.f16.f32 "
                        "{%0,%1,%2,%3},{%4,%5,%6,%7},{%8,%9},{%0,%1,%2,%3};"
                        : "+f"(acc[mi][nj][0]), "+f"(acc[mi][nj][1]),
                          "+f"(acc[mi][nj][2]), "+f"(acc[mi][nj][3])
                        : "r"(aF[mi][0]), "r"(aF[mi][1]), "r"(aF[mi][2]), "r"(aF[mi][3]),
                          "r"(bF[nj][0]), "r"(bF[nj][1]));
        }
    };

#define STEP_PF(CSOFF, PSOFF)                                        \
    asm volatile("cp.async.wait_group 1;" ::: "memory");             \
    __syncthreads();                                                 \
    LOAD_TILE(PSOFF);                                                \
    compute_stage(CSOFF);

    // prologue: stages 0,1 <- iters 0,1
    LOAD_TILE(0);
    LOAD_TILE(STAGE_BYTES);

    // steady: iters 0..59 in groups of 3 (stage bases are immediates)
    for (int itb = 0; itb < 60; itb += 3) {
        STEP_PF(0,               2 * STAGE_BYTES);
        STEP_PF(STAGE_BYTES,     0);
        STEP_PF(2 * STAGE_BYTES, STAGE_BYTES);
    }
    // it=60, it=61
    STEP_PF(0,           2 * STAGE_BYTES);
    STEP_PF(STAGE_BYTES, 0);
    // it=62 (no prefetch)
    asm volatile("cp.async.wait_group 1;" ::: "memory");
    __syncthreads();
    compute_stage(2 * STAGE_BYTES);
    // it=63 (full drain)
    asm volatile("cp.async.wait_group 0;" ::: "memory");
    __syncthreads();
    compute_stage(0);

#undef STEP_PF
#undef LOAD_TILE

    // epilogue: apply per-token scale + bias, direct GMEM stores (float2)
    const int mrow = row0 + wm * 64 + g;
    const int ncol = col0 + wn * 64 + tg * 2;
#pragma unroll
    for (int mi = 0; mi < 4; mi++) {
        const int r = mrow + mi * 16;
        const float s0 = g_sx[r], s1 = g_sx[r + 8];
#pragma unroll
        for (int nj = 0; nj < 8; nj++) {
            const int c = ncol + nj * 8;
            const float b0 = bias[c], b1 = bias[c + 1];
            float2 v0 = make_float2(acc[mi][nj][0] * s0 + b0,
                                    acc[mi][nj][1] * s0 + b1);
            float2 v1 = make_float2(acc[mi][nj][2] * s1 + b0,
                                    acc[mi][nj][3] * s1 + b1);
            *(float2*)(out + (size_t)r * N_TOTAL + c) = v0;
            *(float2*)(out + (size_t)(r + 8) * N_TOTAL + c) = v1;
        }
    }
}

// ------------------------------------------------------------------
// launch
// ------------------------------------------------------------------
extern "C" void kernel_launch(void* const* d_in, const int* in_sizes, int n_in,
                              void* d_out, int out_size) {
    const float* x      = (const float*)d_in[0];
    const void*  w      = d_in[1];
    const float* scales = (const float*)d_in[2];
    const float* zeros  = (const float*)d_in[3];
    const float* bias   = (const float*)d_in[4];
    float* out = (float*)d_out;

    sniff_kernel<<<1, 256>>>((const int*)w);
    quant_kernel<<<M_TOTAL, 256>>>(x);
    wdq_kernel<<<(N_TOTAL * (K_TOTAL / 8)) / 256, 256>>>(w, scales, zeros);

    cudaFuncSetAttribute(gemm_kernel, cudaFuncAttributeMaxDynamicSharedMemorySize,
                         SMEM_BYTES);
    gemm_kernel<<<dim3(N_TOTAL / BN, M_TOTAL / BM), 128, SMEM_BYTES>>>(bias, out);
}

// round 15
// speedup vs baseline: 1.1287x; 1.1287x over previous
#include <cuda_runtime.h>
#include <cuda_fp16.h>
#include <stdint.h>

// ------------------------------------------------------------------
// Problem constants
// ------------------------------------------------------------------
#define M_TOTAL 8192      // B*S = 4*2048 tokens
#define N_TOTAL 4096      // OUT
#define K_TOTAL 4096      // IN
#define GRP     256

#define BM 64
#define BN 128
#define BK 64             // halves per K-chunk (128 bytes/row -> SW128)
#define KITERS (K_TOTAL / BK)   // 64
#define A_BYTES 8192            // 64 rows x 128 B
#define B_BYTES 16384           // 128 rows x 128 B
#define STAGE_BYTES (A_BYTES + B_BYTES)          // 24 KB
#define SMEM_BYTES (3 * STAGE_BYTES)             // 72 KB -> 3 CTAs/SM

// ------------------------------------------------------------------
// Scratch (device globals; no allocation allowed)
// ------------------------------------------------------------------
__device__ __half g_aq[(size_t)M_TOTAL * K_TOTAL];   // (q - zp), exact in fp16
__device__ __half g_w16[(size_t)N_TOTAL * K_TOTAL];  // (w - zero)*scale in fp16
__device__ float  g_sx[M_TOTAL];                     // per-token scale
__device__ int    g_w_is_int8;                       // weight buffer dtype flag

// ------------------------------------------------------------------
// helpers
// ------------------------------------------------------------------
__device__ __forceinline__ uint32_t smem_u32(const void* p) {
    uint32_t a;
    asm("{ .reg .u64 t; cvta.to.shared.u64 t, %1; cvt.u32.u64 %0, t; }"
        : "=r"(a) : "l"(p));
    return a;
}

__device__ __forceinline__ uint32_t swz(uint32_t off) {
    return off ^ ((off >> 3) & 0x70);
}

// ldmatrix.x4 with compile-time byte offset folded into the operand
#define LDSM_X4_OFF(ADDR, OFF, R0, R1, R2, R3)                                   \
    asm volatile("ldmatrix.sync.aligned.m8n8.x4.shared.b16 {%0,%1,%2,%3}, [%4+" #OFF "];" \
                 : "=r"(R0), "=r"(R1), "=r"(R2), "=r"(R3) : "r"(ADDR))

#define MMA_16816(ACC, AF, B0, B1)                                               \
    asm volatile("mma.sync.aligned.m16n8k16.row.col.f32.f16.f16.f32 "            \
        "{%0,%1,%2,%3},{%4,%5,%6,%7},{%8,%9},{%0,%1,%2,%3};"                     \
        : "+f"((ACC)[0]), "+f"((ACC)[1]), "+f"((ACC)[2]), "+f"((ACC)[3])         \
        : "r"((AF)[0]), "r"((AF)[1]), "r"((AF)[2]), "r"((AF)[3]),                \
          "r"(B0), "r"(B1))

// ------------------------------------------------------------------
// Kernel 0: detect weight buffer dtype (int32-promoted vs raw int8)
// ------------------------------------------------------------------
__global__ void sniff_kernel(const int* __restrict__ w) {
    __shared__ int bad;
    if (threadIdx.x == 0) bad = 0;
    __syncthreads();
    int v = w[threadIdx.x * 16000];
    if (v < -8 || v > 7) atomicOr(&bad, 1);
    __syncthreads();
    if (threadIdx.x == 0) g_w_is_int8 = bad;
}

// ------------------------------------------------------------------
// Kernel 1: per-token asymmetric int8 fake-quant -> (q - zp) in fp16
// ------------------------------------------------------------------
__global__ void __launch_bounds__(256) quant_kernel(const float* __restrict__ x) {
    const int t = blockIdx.x;
    const int tid = threadIdx.x;
    const float4* xp = (const float4*)x + (size_t)t * (K_TOTAL / 4);

    float4 v[4];
    float mn = 0.0f, mx = 0.0f;
#pragma unroll
    for (int i = 0; i < 4; i++) {
        v[i] = xp[i * 256 + tid];
        mn = fminf(mn, fminf(fminf(v[i].x, v[i].y), fminf(v[i].z, v[i].w)));
        mx = fmaxf(mx, fmaxf(fmaxf(v[i].x, v[i].y), fmaxf(v[i].z, v[i].w)));
    }
#pragma unroll
    for (int o = 16; o; o >>= 1) {
        mn = fminf(mn, __shfl_xor_sync(0xffffffffu, mn, o));
        mx = fmaxf(mx, __shfl_xor_sync(0xffffffffu, mx, o));
    }
    __shared__ float smn[8], smx[8], s_scale, s_zp;
    const int wid = tid >> 5, lid = tid & 31;
    if (lid == 0) { smn[wid] = mn; smx[wid] = mx; }
    __syncthreads();
    if (tid == 0) {
        float a = smn[0], b = smx[0];
#pragma unroll
        for (int i = 1; i < 8; i++) { a = fminf(a, smn[i]); b = fmaxf(b, smx[i]); }
        float scale = fmaxf((b - a) / 255.0f, 1.1920929e-07f);
        float zp = -128.0f - rintf(a / scale);
        zp = fminf(fmaxf(zp, -128.0f), 127.0f);
        s_scale = scale; s_zp = zp;
        g_sx[t] = scale;
    }
    __syncthreads();
    const float scale = s_scale, zp = s_zp;

    __half* aqp = g_aq + (size_t)t * K_TOTAL;
#pragma unroll
    for (int i = 0; i < 4; i++) {
        float qx = fminf(fmaxf(rintf(v[i].x / scale) + zp, -128.0f), 127.0f) - zp;
        float qy = fminf(fmaxf(rintf(v[i].y / scale) + zp, -128.0f), 127.0f) - zp;
        float qz = fminf(fmaxf(rintf(v[i].z / scale) + zp, -128.0f), 127.0f) - zp;
        float qw = fminf(fmaxf(rintf(v[i].w / scale) + zp, -128.0f), 127.0f) - zp;
        __half2 h0 = __floats2half2_rn(qx, qy);
        __half2 h1 = __floats2half2_rn(qz, qw);
        uint2 u;
        u.x = *reinterpret_cast<uint32_t*>(&h0);
        u.y = *reinterpret_cast<uint32_t*>(&h1);
        ((uint2*)aqp)[i * 256 + tid] = u;
    }
}

// ------------------------------------------------------------------
// Kernel 2: groupwise int4 weight dequant -> fp16 (dtype-adaptive)
// ------------------------------------------------------------------
__global__ void __launch_bounds__(256) wdq_kernel(const void* __restrict__ wraw,
                                                  const float* __restrict__ scales,
                                                  const float* __restrict__ zeros) {
    const int idx = blockIdx.x * 256 + threadIdx.x;
    const size_t base = (size_t)idx * 8;
    const int o = (int)(base >> 12);
    const int g = (int)((base & (K_TOTAL - 1)) >> 8);
    const float s = scales[o * (K_TOTAL / GRP) + g];
    const float z = zeros[o * (K_TOTAL / GRP) + g];

    float wv[8];
    if (g_w_is_int8) {
        const char4* wp = (const char4*)((const int8_t*)wraw + base);
        char4 c0 = wp[0], c1 = wp[1];
        wv[0] = c0.x; wv[1] = c0.y; wv[2] = c0.z; wv[3] = c0.w;
        wv[4] = c1.x; wv[5] = c1.y; wv[6] = c1.z; wv[7] = c1.w;
    } else {
        const int4* wp = (const int4*)((const int*)wraw + base);
        int4 a = wp[0], b = wp[1];
        wv[0] = (float)a.x; wv[1] = (float)a.y; wv[2] = (float)a.z; wv[3] = (float)a.w;
        wv[4] = (float)b.x; wv[5] = (float)b.y; wv[6] = (float)b.z; wv[7] = (float)b.w;
    }

    __half2 h0 = __floats2half2_rn((wv[0] - z) * s, (wv[1] - z) * s);
    __half2 h1 = __floats2half2_rn((wv[2] - z) * s, (wv[3] - z) * s);
    __half2 h2 = __floats2half2_rn((wv[4] - z) * s, (wv[5] - z) * s);
    __half2 h3 = __floats2half2_rn((wv[6] - z) * s, (wv[7] - z) * s);
    uint4 u;
    u.x = *reinterpret_cast<uint32_t*>(&h0);
    u.y = *reinterpret_cast<uint32_t*>(&h1);
    u.z = *reinterpret_cast<uint32_t*>(&h2);
    u.w = *reinterpret_cast<uint32_t*>(&h3);
    *((uint4*)(g_w16 + base)) = u;
}

// ------------------------------------------------------------------
// Kernel 3: HMMA fp16 GEMM, 64x128 CTA tile, 128 threads (4 warps,
// 2x2 grid, 32x64 warp tile), 3-stage cp.async, unroll-by-3 mainloop,
// single-base XOR addressing, ldsm/MMA hand-interleaved so post-
// barrier LDS latency is hidden behind independent MMAs. 3 CTAs/SM.
// ------------------------------------------------------------------
__global__ void __launch_bounds__(128, 3) gemm_kernel(const float* __restrict__ bias,
                                                      float* __restrict__ out) {
    extern __shared__ char smem[];
    const uint32_t sb = smem_u32(smem);
    const int tid = threadIdx.x;
    const int lane = tid & 31, wid = tid >> 5;
    const int wm = wid >> 1, wn = wid & 1;           // warp grid 2 x 2
    const int g = lane >> 2, tg = lane & 3;
    const int row0 = blockIdx.y * BM;                // token (M)
    const int col0 = blockIdx.x * BN;                // out-feature (N)

    float acc[2][8][4];
#pragma unroll
    for (int a = 0; a < 2; a++)
#pragma unroll
        for (int b = 0; b < 8; b++)
#pragma unroll
            for (int c = 0; c < 4; c++) acc[a][b][c] = 0.0f;

    // advancing cp.async source pointers (+8 uint4 = 128 B per K-iter)
    const int ldr = tid >> 3, ldc = tid & 7;         // 16 rows x 8 cols of 16B
    const uint4* gA = (const uint4*)g_aq  + (size_t)(row0 + ldr) * 512 + ldc;
    const uint4* gB = (const uint4*)g_w16 + (size_t)(col0 + ldr) * 512 + ldc;
    const uint32_t sdst = sb + swz(ldr * 128 + ldc * 16);

#define LOAD_TILE(SOFF)                                                        \
    {                                                                          \
        _Pragma("unroll")                                                      \
        for (int i = 0; i < 4; i++)                                            \
            asm volatile("cp.async.cg.shared.global [%0], [%1], 16;"           \
                :: "r"(sdst + (SOFF) + i * 2048), "l"(gA + i * 8192));         \
        _Pragma("unroll")                                                      \
        for (int i = 0; i < 8; i++)                                            \
            asm volatile("cp.async.cg.shared.global [%0], [%1], 16;"           \
                :: "r"(sdst + (SOFF) + A_BYTES + i * 2048), "l"(gB + i * 8192));\
        asm volatile("cp.async.commit_group;" ::: "memory");                   \
        gA += 8; gB += 8;                                                      \
    }

    // single base register per operand (stage offset is an immediate)
    const uint32_t aRow = wm * 32 + (lane & 15);
    const uint32_t bRow = wn * 64 + (lane & 15);
    const uint32_t laneHalf = lane >> 4;             // 0 or 1 (k or k+8)
    const uint32_t Abase = sb + aRow * 128 + ((laneHalf ^ (aRow & 7)) * 16);
    const uint32_t Bbase = sb + A_BYTES + bRow * 128 + ((laneHalf ^ (bRow & 7)) * 16);

    auto compute_stage = [&](const uint32_t so) {
        const uint32_t As = Abase + so;
        const uint32_t Bs = Bbase + so;
#pragma unroll
        for (int kk = 0; kk < 4; kk++) {
            const uint32_t xa = As ^ (kk * 32);
            const uint32_t xb = Bs ^ (kk * 32);
            uint32_t aF[2][4], bF[8][2];
            // front-load A and first B batch
            LDSM_X4_OFF(xa, 0,    aF[0][0], aF[0][1], aF[0][2], aF[0][3]);
            LDSM_X4_OFF(xa, 2048, aF[1][0], aF[1][1], aF[1][2], aF[1][3]);
            {
                uint32_t r0, r1, r2, r3;
                LDSM_X4_OFF(xb, 0, r0, r1, r2, r3);
                bF[0][0] = r0; bF[0][1] = r2; bF[1][0] = r1; bF[1][1] = r3;
            }
            {   // issue B batch 1, then run MMAs on batch 0 while it lands
                uint32_t r0, r1, r2, r3;
                LDSM_X4_OFF(xb, 2048, r0, r1, r2, r3);
                MMA_16816(acc[0][0], aF[0], bF[0][0], bF[0][1]);
                MMA_16816(acc[1][0], aF[1], bF[0][0], bF[0][1]);
                MMA_16816(acc[0][1], aF[0], bF[1][0], bF[1][1]);
                MMA_16816(acc[1][1], aF[1], bF[1][0], bF[1][1]);
                bF[2][0] = r0; bF[2][1] = r2; bF[3][0] = r1; bF[3][1] = r3;
            }
            {   // issue B batch 2, run MMAs on batch 1
                uint32_t r0, r1, r2, r3;
                LDSM_X4_OFF(xb, 4096, r0, r1, r2, r3);
                MMA_16816(acc[0][2], aF[0], bF[2][0], bF[2][1]);
                MMA_16816(acc[1][2], aF[1], bF[2][0], bF[2][1]);
                MMA_16816(acc[0][3], aF[0], bF[3][0], bF[3][1]);
                MMA_16816(acc[1][3], aF[1], bF[3][0], bF[3][1]);
                bF[4][0] = r0; bF[4][1] = r2; bF[5][0] = r1; bF[5][1] = r3;
            }
            {   // issue B batch 3, run MMAs on batch 2
                uint32_t r0, r1, r2, r3;
                LDSM_X4_OFF(xb, 6144, r0, r1, r2, r3);
                MMA_16816(acc[0][4], aF[0], bF[4][0], bF[4][1]);
                MMA_16816(acc[1][4], aF[1], bF[4][0], bF[4][1]);
                MMA_16816(acc[0][5], aF[0], bF[5][0], bF[5][1]);
                MMA_16816(acc[1][5], aF[1], bF[5][0], bF[5][1]);
                bF[6][0] = r0; bF[6][1] = r2; bF[7][0] = r1; bF[7][1] = r3;
            }
            MMA_16816(acc[0][6], aF[0], bF[6][0], bF[6][1]);
            MMA_16816(acc[1][6], aF[1], bF[6][0], bF[6][1]);
            MMA_16816(acc[0][7], aF[0], bF[7][0], bF[7][1]);
            MMA_16816(acc[1][7], aF[1], bF[7][0], bF[7][1]);
        }
    };

#define STEP_PF(CSOFF, PSOFF)                                        \
    asm volatile("cp.async.wait_group 1;" ::: "memory");             \
    __syncthreads();                                                 \
    LOAD_TILE(PSOFF);                                                \
    compute_stage(CSOFF);

    // prologue: stages 0,1 <- iters 0,1
    LOAD_TILE(0);
    LOAD_TILE(STAGE_BYTES);

    // steady: iters 0..59 in groups of 3 (stage bases are immediates)
    for (int itb = 0; itb < 60; itb += 3) {
        STEP_PF(0,               2 * STAGE_BYTES);
        STEP_PF(STAGE_BYTES,     0);
        STEP_PF(2 * STAGE_BYTES, STAGE_BYTES);
    }
    // it=60, it=61
    STEP_PF(0,           2 * STAGE_BYTES);
    STEP_PF(STAGE_BYTES, 0);
    // it=62 (no prefetch)
    asm volatile("cp.async.wait_group 1;" ::: "memory");
    __syncthreads();
    compute_stage(2 * STAGE_BYTES);
    // it=63 (full drain)
    asm volatile("cp.async.wait_group 0;" ::: "memory");
    __syncthreads();
    compute_stage(0);

#undef STEP_PF
#undef LOAD_TILE

    // epilogue: apply per-token scale + bias, direct GMEM stores (float2)
    const int mrow = row0 + wm * 32 + g;
    const int ncol = col0 + wn * 64 + tg * 2;
#pragma unroll
    for (int mi = 0; mi < 2; mi++) {
        const int r = mrow + mi * 16;
        const float s0 = g_sx[r], s1 = g_sx[r + 8];
#pragma unroll
        for (int nj = 0; nj < 8; nj++) {
            const int c = ncol + nj * 8;
            const float b0 = bias[c], b1 = bias[c + 1];
            float2 v0 = make_float2(acc[mi][nj][0] * s0 + b0,
                                    acc[mi][nj][1] * s0 + b1);
            float2 v1 = make_float2(acc[mi][nj][2] * s1 + b0,
                                    acc[mi][nj][3] * s1 + b1);
            *(float2*)(out + (size_t)r * N_TOTAL + c) = v0;
            *(float2*)(out + (size_t)(r + 8) * N_TOTAL + c) = v1;
        }
    }
}

// ------------------------------------------------------------------
// launch
// ------------------------------------------------------------------
extern "C" void kernel_launch(void* const* d_in, const int* in_sizes, int n_in,
                              void* d_out, int out_size) {
    const float* x      = (const float*)d_in[0];
    const void*  w      = d_in[1];
    const float* scales = (const float*)d_in[2];
    const float* zeros  = (const float*)d_in[3];
    const float* bias   = (const float*)d_in[4];
    float* out = (float*)d_out;

    sniff_kernel<<<1, 256>>>((const int*)w);
    quant_kernel<<<M_TOTAL, 256>>>(x);
    wdq_kernel<<<(N_TOTAL * (K_TOTAL / 8)) / 256, 256>>>(w, scales, zeros);

    cudaFuncSetAttribute(gemm_kernel, cudaFuncAttributeMaxDynamicSharedMemorySize,
                         SMEM_BYTES);
    gemm_kernel<<<dim3(N_TOTAL / BN, M_TOTAL / BM), 128, SMEM_BYTES>>>(bias, out);
}